// round 16
// baseline (speedup 1.0000x reference)
#include <cuda_runtime.h>
#include <math.h>

// Problem constants
#define NTOK   16384      // B*S
#define NF     32         // features
#define NH     8          // hidden
#define ND     300        // n_dim_model
#define N2D    600        // 2*D
#define NWARP  10
#define NTHR   320
#define TOKS   16         // tokens per block
#define HTOK   8          // tokens per phase-4 half-pass

// Shared layout (float offsets)
#define S_PRET 0          // [256][16] prescaler transposed             (4096)
#define S_H1   4096       // [32 f][8 j][16 t] h1 (no duplication)      (4096)
#define S_WT   8192       // [32 f][16 t] softmax weights transposed    (512)
#define S_PART 8704       // [10 w][8 t] float2 LN partials             (160)
#define S_STAT 8864       // [8 t] float2 (mean, inv)                   (16)
#define S_FLW  8880       // [256][32] fl_fc1_w staging                 (8192)
#define SMEMF  17072      // total floats (68288 bytes)

// Lane-sliced fused gate weights: [f][warp][chunk(5)][lane(32)][4 floats]
// Per-lane record (d = warp*32+lane), 20 floats:
//   floats 0..15 : (wA_j, wB_j) pairs, j=0..7
//   floats 16,17 : fused gate bias (gA, gB) = b2@Wg + bg
//   floats 18,19 : ln_g, ln_b
// Pad region d in [300,320) never written -> stays zero (zero-init globals).
__device__ float g_W2[NF * NWARP * 5 * 32 * 4];   // 819 KB

// ---------------------------------------------------------------------------
// packed f32x2 + fast-math helpers (sm_100+)
// ---------------------------------------------------------------------------
__device__ __forceinline__ unsigned long long ffma2(unsigned long long a,
                                                    unsigned long long b,
                                                    unsigned long long c) {
    unsigned long long d;
    asm("fma.rn.f32x2 %0, %1, %2, %3;" : "=l"(d) : "l"(a), "l"(b), "l"(c));
    return d;
}
__device__ __forceinline__ unsigned long long fadd2(unsigned long long a,
                                                    unsigned long long b) {
    unsigned long long d;
    asm("add.rn.f32x2 %0, %1, %2;" : "=l"(d) : "l"(a), "l"(b));
    return d;
}
__device__ __forceinline__ unsigned long long pack2(float lo, float hi) {
    unsigned long long r;
    asm("mov.b64 %0, {%1, %2};" : "=l"(r) : "f"(lo), "f"(hi));
    return r;
}
__device__ __forceinline__ void unpack2(unsigned long long v, float& lo, float& hi) {
    asm("mov.b64 {%0, %1}, %2;" : "=f"(lo), "=f"(hi) : "l"(v));
}
__device__ __forceinline__ float frcp_fast(float x) {
    float r;
    asm("rcp.approx.f32 %0, %1;" : "=f"(r) : "f"(x));
    return r;
}

// ---------------------------------------------------------------------------
// Packed folding 8-token warp reduction: sp[t] holds (y, y*y) for token t.
// Returns packed (sum, sq) over all 32 lanes for token (lane>>2).
// ---------------------------------------------------------------------------
__device__ __forceinline__ unsigned long long fold8p(unsigned long long s[HTOK],
                                                     int lane) {
    {   const bool hi = (lane & 16) != 0;
        #pragma unroll
        for (int i = 0; i < 4; ++i) {
            unsigned long long sv = hi ? s[i] : s[i + 4];
            unsigned long long rv = __shfl_xor_sync(0xffffffffu, sv, 16);
            s[i] = fadd2(hi ? s[i + 4] : s[i], rv);
        }
    }
    {   const bool hi = (lane & 8) != 0;
        #pragma unroll
        for (int i = 0; i < 2; ++i) {
            unsigned long long sv = hi ? s[i] : s[i + 2];
            unsigned long long rv = __shfl_xor_sync(0xffffffffu, sv, 8);
            s[i] = fadd2(hi ? s[i + 2] : s[i], rv);
        }
    }
    {   const bool hi = (lane & 4) != 0;
        unsigned long long sv = hi ? s[0] : s[1];
        unsigned long long rv = __shfl_xor_sync(0xffffffffu, sv, 4);
        s[0] = fadd2(hi ? s[1] : s[0], rv);
    }
    s[0] = fadd2(s[0], __shfl_xor_sync(0xffffffffu, s[0], 2));
    return fadd2(s[0], __shfl_xor_sync(0xffffffffu, s[0], 1));
}

// ---------------------------------------------------------------------------
// Kernel A: fuse W2@Wg (+ bias row) into the lane-sliced record layout.
// grid (32, 9), block 256
// ---------------------------------------------------------------------------
__global__ void fuse_weights_kernel(const float* __restrict__ W2,   // [F,8,300]
                                    const float* __restrict__ b2,   // [F,300]
                                    const float* __restrict__ Wg,   // [F,300,600]
                                    const float* __restrict__ bg,   // [F,600]
                                    const float* __restrict__ lng,  // [F,300]
                                    const float* __restrict__ lnb)  // [F,300]
{
    int f = blockIdx.x;
    int j = blockIdx.y;  // 0..8 (8 == bias row)
    __shared__ float s_a[ND];
    const float* wgf = Wg + (size_t)f * (ND * N2D);
    for (int k = threadIdx.x; k < ND; k += blockDim.x)
        s_a[k] = (j < 8) ? W2[f * (NH * ND) + j * ND + k] : b2[f * ND + k];
    __syncthreads();
    for (int n = threadIdx.x; n < N2D; n += blockDim.x) {
        float acc = 0.f;
        #pragma unroll 4
        for (int k = 0; k < ND; ++k)
            acc = fmaf(s_a[k], wgf[k * N2D + n], acc);
        if (j == 8) acc += bg[f * N2D + n];
        int d   = (n < ND) ? n : (n - ND);
        int hb  = (n < ND) ? 0 : 1;
        int idx = (j < 8) ? (2 * j + hb) : (16 + hb);
        int w   = d >> 5, lane = d & 31;
        g_W2[((((f * NWARP + w) * 5) + (idx >> 2)) << 7) + (lane << 2) + (idx & 3)] = acc;
    }
    if (j == 8) {
        for (int d = threadIdx.x; d < ND; d += blockDim.x) {
            int w = d >> 5, lane = d & 31;
            int base = ((((f * NWARP + w) * 5) + 4) << 7) + (lane << 2);
            g_W2[base + 2] = lng[f * ND + d];
            g_W2[base + 3] = lnb[f * ND + d];
        }
    }
}

// ---------------------------------------------------------------------------
// Kernel B: fused VSN forward. 16 tokens/block, 320 threads (10 warps).
// Phase 4: two-sync structure, packed fold, pipelined weight LDGs, direct
// ulonglong2 h1 loads, and QUAD RECIPROCAL SHARING in the sigmoid (one
// rcp.approx serves 4 sigmoids — MUFU per iter 32 -> 20).
// ---------------------------------------------------------------------------
__global__ void __launch_bounds__(NTHR, 2)
vsn_main_kernel(const float* __restrict__ x,        // [NTOK, 32]
                const float* __restrict__ pre_w,    // [32,8]
                const float* __restrict__ pre_b,    // [32,8]
                const float* __restrict__ fc1w,     // [32,8,8]
                const float* __restrict__ fc1b,     // [32,8]
                const float* __restrict__ fl_fc1_w, // [256,32]
                const float* __restrict__ fl_fc1_b, // [32]
                const float* __restrict__ fl_fc2_w, // [32,32]
                const float* __restrict__ fl_fc2_b, // [32]
                const float* __restrict__ fl_gate_w,// [32,64]
                const float* __restrict__ fl_gate_b,// [64]
                const float* __restrict__ fl_ln_g,  // [32]
                const float* __restrict__ fl_ln_b,  // [32]
                float* __restrict__ out,            // [NTOK,300]
                float* __restrict__ out_w)          // [NTOK,32]
{
    extern __shared__ float smem[];
    const int tid  = threadIdx.x;
    const int lane = tid & 31;
    const int warp = tid >> 5;
    const int token_base = blockIdx.x * TOKS;

    // ---- Phase 1: prescaler into s_preT (stride 16), stage fl_fc1_w ----
    for (int idx = tid; idx < 4096; idx += NTHR) {
        int t = idx & 15, r = idx >> 4, f = r >> 3;
        smem[S_PRET + r * 16 + t] =
            fmaf(x[(token_base + t) * 32 + f], pre_w[r], pre_b[r]);
    }
    {
        const float4* src = (const float4*)fl_fc1_w;
        float4* dst = (float4*)(smem + S_FLW);
        for (int i = tid; i < 2048; i += NTHR) dst[i] = src[i];
    }
    __syncthreads();

    // ---- Phase 2: h1 = elu(pre @ fc1 + b) into [f][j][16 t] (no dup) ----
    for (int idx = tid; idx < 4096; idx += NTHR) {
        int t = idx & 15, r = idx >> 4, f = r >> 3, k = r & 7;
        float acc = fc1b[r];
        #pragma unroll
        for (int h = 0; h < 8; ++h)
            acc = fmaf(smem[S_PRET + ((f << 3) + h) * 16 + t],
                       fc1w[(f << 6) + (h << 3) + k], acc);
        float e = acc > 0.f ? acc : expm1f(acc);
        smem[S_H1 + ((f << 3) + k) * 16 + t] = e;
    }

    // ---- Phase 3: flattened GRN + softmax (warps 0..7, 2 tokens each) ----
    if (warp < 8) {
        const int t0 = warp * 2, t1 = t0 + 1;
        float b1 = fl_fc1_b[lane];
        float a0 = b1, a1 = b1;
        // token pair loaded as one LDS.64 (t0 even, adjacent in row)
        #pragma unroll 4
        for (int i = 0; i < 256; ++i) {
            float w = smem[S_FLW + i * 32 + lane];
            float2 p = *(const float2*)(smem + S_PRET + i * 16 + t0);
            a0 = fmaf(p.x, w, a0);
            a1 = fmaf(p.y, w, a1);
        }
        a0 = a0 > 0.f ? a0 : expm1f(a0);
        a1 = a1 > 0.f ? a1 : expm1f(a1);

        float c0 = fl_fc2_b[lane], c1 = c0;
        #pragma unroll
        for (int j = 0; j < 32; ++j) {
            float w = fl_fc2_w[j * 32 + lane];
            c0 = fmaf(__shfl_sync(0xffffffffu, a0, j), w, c0);
            c1 = fmaf(__shfl_sync(0xffffffffu, a1, j), w, c1);
        }

        float ga0 = fl_gate_b[lane], gb0 = fl_gate_b[lane + 32];
        float ga1 = ga0, gb1 = gb0;
        #pragma unroll
        for (int k = 0; k < 32; ++k) {
            float wa = fl_gate_w[k * 64 + lane];
            float wb = fl_gate_w[k * 64 + lane + 32];
            float v0 = __shfl_sync(0xffffffffu, c0, k);
            float v1 = __shfl_sync(0xffffffffu, c1, k);
            ga0 = fmaf(v0, wa, ga0); gb0 = fmaf(v0, wb, gb0);
            ga1 = fmaf(v1, wa, ga1); gb1 = fmaf(v1, wb, gb1);
        }
        float glu0 = __fdividef(ga0, 1.f + __expf(-gb0));
        float glu1 = __fdividef(ga1, 1.f + __expf(-gb1));

        // interp(flat, 256 -> 32)
        float pos = (float)lane * (255.0f / 31.0f);
        int lo = (int)floorf(pos); if (lo > 255) lo = 255;
        int hi = min(lo + 1, 255);
        float wd = pos - (float)lo;
        float2 plo = *(const float2*)(smem + S_PRET + lo * 16 + t0);
        float2 phi = *(const float2*)(smem + S_PRET + hi * 16 + t0);
        float r0 = plo.x * (1.f - wd) + phi.x * wd;
        float r1 = plo.y * (1.f - wd) + phi.y * wd;

        float y0 = glu0 + r0, y1 = glu1 + r1;
        float s0 = y0, q0 = y0 * y0, s1 = y1, q1 = y1 * y1;
        #pragma unroll
        for (int o = 16; o > 0; o >>= 1) {
            s0 += __shfl_xor_sync(0xffffffffu, s0, o);
            q0 += __shfl_xor_sync(0xffffffffu, q0, o);
            s1 += __shfl_xor_sync(0xffffffffu, s1, o);
            q1 += __shfl_xor_sync(0xffffffffu, q1, o);
        }
        float m0 = s0 * (1.f / 32.f), v0 = q0 * (1.f / 32.f) - m0 * m0;
        float m1 = s1 * (1.f / 32.f), v1 = q1 * (1.f / 32.f) - m1 * m1;
        float wl0 = (y0 - m0) * rsqrtf(v0 + 1e-5f) * fl_ln_g[lane] + fl_ln_b[lane];
        float wl1 = (y1 - m1) * rsqrtf(v1 + 1e-5f) * fl_ln_g[lane] + fl_ln_b[lane];

        float mx0 = wl0, mx1 = wl1;
        #pragma unroll
        for (int o = 16; o > 0; o >>= 1) {
            mx0 = fmaxf(mx0, __shfl_xor_sync(0xffffffffu, mx0, o));
            mx1 = fmaxf(mx1, __shfl_xor_sync(0xffffffffu, mx1, o));
        }
        float e0 = __expf(wl0 - mx0), e1 = __expf(wl1 - mx1);
        float se0 = e0, se1 = e1;
        #pragma unroll
        for (int o = 16; o > 0; o >>= 1) {
            se0 += __shfl_xor_sync(0xffffffffu, se0, o);
            se1 += __shfl_xor_sync(0xffffffffu, se1, o);
        }
        float w0 = __fdividef(e0, se0), w1 = __fdividef(e1, se1);
        smem[S_WT + lane * 16 + t0] = w0;
        smem[S_WT + lane * 16 + t1] = w1;
        out_w[(token_base + t0) * 32 + lane] = w0;
        out_w[(token_base + t1) * 32 + lane] = w1;
    }
    __syncthreads();

    // ---- Phase 4: two passes of 8 tokens; lane owns d = warp*32+lane ----
    const int d = (warp << 5) + lane;
    const float actmask = (d < ND) ? 1.0f : 0.0f;
    float posd = (float)d * (7.0f / 299.0f);
    int lod = (int)floorf(posd); if (lod > 7) lod = 7;
    int hid = min(lod + 1, 7);
    float wdd = posd - (float)lod;

    const float* wlane = g_W2 + ((warp * 5) << 7) + (lane << 2);  // f=0 base
    const int    fstep = NWARP * 5 * 128;                          // floats per f

    #pragma unroll 1
    for (int half = 0; half < 2; ++half) {
        const int tbase = half * HTOK;

        float acc[HTOK];
        #pragma unroll
        for (int t = 0; t < HTOK; ++t) acc[t] = 0.f;

        // preload f=0 weight record
        ulonglong2 q0 = *(const ulonglong2*)(wlane);
        ulonglong2 q1 = *(const ulonglong2*)(wlane + 128);
        ulonglong2 q2 = *(const ulonglong2*)(wlane + 256);
        ulonglong2 q3 = *(const ulonglong2*)(wlane + 384);
        ulonglong2 q4 = *(const ulonglong2*)(wlane + 512);

        #pragma unroll 1
        for (int f = 0; f < NF; ++f) {
            // extract all scalars needed after the q overwrite
            float gab, gbb, lng, lnb;
            unpack2(q4.x, gab, gbb);
            unpack2(q4.y, lng, lnb);

            // interp residuals for this half's 8 tokens (float4 rows)
            float s[HTOK];
            {
                const float4* pl4 =
                    (const float4*)(smem + S_PRET + ((f << 3) + lod) * 16 + tbase);
                const float4* ph4 =
                    (const float4*)(smem + S_PRET + ((f << 3) + hid) * 16 + tbase);
                #pragma unroll
                for (int c = 0; c < 2; ++c) {
                    float4 a = pl4[c], b = ph4[c];
                    s[4 * c + 0] = fmaf(wdd, b.x - a.x, a.x);
                    s[4 * c + 1] = fmaf(wdd, b.y - a.y, a.y);
                    s[4 * c + 2] = fmaf(wdd, b.z - a.z, a.z);
                    s[4 * c + 3] = fmaf(wdd, b.w - a.w, a.w);
                }
            }

            // gate: token-pair packed accumulators; h1 pairs loaded directly
            unsigned long long Ab = pack2(gab, gab), Bb = pack2(gbb, gbb);
            unsigned long long A0 = Ab, A1 = Ab, A2 = Ab, A3 = Ab;
            unsigned long long B0 = Bb, B1 = Bb, B2 = Bb, B3 = Bb;

            const float* h1r = smem + S_H1 + (f << 7) + tbase;  // row stride 16

            #define GATE_J(QJ, ROW) do {                                        \
                float wa_, wb_; unpack2((QJ), wa_, wb_);                        \
                unsigned long long wad_ = pack2(wa_, wa_);                      \
                unsigned long long wbd_ = pack2(wb_, wb_);                      \
                ulonglong2 hA_ = *(const ulonglong2*)(ROW);                     \
                ulonglong2 hB_ = *(const ulonglong2*)((ROW) + 4);               \
                A0 = ffma2(hA_.x, wad_, A0);  B0 = ffma2(hA_.x, wbd_, B0);      \
                A1 = ffma2(hA_.y, wad_, A1);  B1 = ffma2(hA_.y, wbd_, B1);      \
                A2 = ffma2(hB_.x, wad_, A2);  B2 = ffma2(hB_.x, wbd_, B2);      \
                A3 = ffma2(hB_.y, wad_, A3);  B3 = ffma2(hB_.y, wbd_, B3);      \
            } while (0)

            GATE_J(q0.x, h1r + 0 * 16);
            GATE_J(q0.y, h1r + 1 * 16);
            GATE_J(q1.x, h1r + 2 * 16);
            GATE_J(q1.y, h1r + 3 * 16);
            GATE_J(q2.x, h1r + 4 * 16);
            GATE_J(q2.y, h1r + 5 * 16);
            GATE_J(q3.x, h1r + 6 * 16);
            GATE_J(q3.y, h1r + 7 * 16);
            #undef GATE_J

            // software pipeline: issue next feature's weight loads NOW
            {
                int fn = (f + 1 < NF) ? (f + 1) : f;
                const float* wn = wlane + fn * fstep;
                q0 = *(const ulonglong2*)(wn);
                q1 = *(const ulonglong2*)(wn + 128);
                q2 = *(const ulonglong2*)(wn + 256);
                q3 = *(const ulonglong2*)(wn + 384);
                q4 = *(const ulonglong2*)(wn + 512);
            }

            // sigmoid with quad reciprocal sharing: one rcp per 4 sigmoids.
            // sigma_i = 1/f_i recovered as rp * (product of the other three).
            float y[HTOK];
            {
                float a0, a1, a2, a3, b0, b1, b2, b3;
                // quad 1: tokens 0..3 (A0/B0, A1/B1)
                unpack2(A0, a0, a1); unpack2(B0, b0, b1);
                unpack2(A1, a2, a3); unpack2(B1, b2, b3);
                {
                    float f0 = 1.f + __expf(-b0);
                    float f1 = 1.f + __expf(-b1);
                    float f2 = 1.f + __expf(-b2);
                    float f3 = 1.f + __expf(-b3);
                    float f01 = f0 * f1, f23 = f2 * f3;
                    float rp  = frcp_fast(f01 * f23);
                    float q01 = rp * f23;   // = 1/(f0*f1)
                    float q23 = rp * f01;   // = 1/(f2*f3)
                    y[0] = (fmaf(a0 * q01, f1, s[0])) * actmask;
                    y[1] = (fmaf(a1 * q01, f0, s[1])) * actmask;
                    y[2] = (fmaf(a2 * q23, f3, s[2])) * actmask;
                    y[3] = (fmaf(a3 * q23, f2, s[3])) * actmask;
                }
                // quad 2: tokens 4..7 (A2/B2, A3/B3)
                unpack2(A2, a0, a1); unpack2(B2, b0, b1);
                unpack2(A3, a2, a3); unpack2(B3, b2, b3);
                {
                    float f0 = 1.f + __expf(-b0);
                    float f1 = 1.f + __expf(-b1);
                    float f2 = 1.f + __expf(-b2);
                    float f3 = 1.f + __expf(-b3);
                    float f01 = f0 * f1, f23 = f2 * f3;
                    float rp  = frcp_fast(f01 * f23);
                    float q01 = rp * f23;
                    float q23 = rp * f01;
                    y[4] = (fmaf(a0 * q01, f1, s[4])) * actmask;
                    y[5] = (fmaf(a1 * q01, f0, s[5])) * actmask;
                    y[6] = (fmaf(a2 * q23, f3, s[6])) * actmask;
                    y[7] = (fmaf(a3 * q23, f2, s[7])) * actmask;
                }
            }

            // packed fold: (sum, sq) for all 8 tokens in one reduction
            unsigned long long sp[HTOK];
            #pragma unroll
            for (int t = 0; t < HTOK; ++t) sp[t] = pack2(y[t], y[t] * y[t]);
            unsigned long long pv = fold8p(sp, lane);
            if ((lane & 3) == 0)
                *(unsigned long long*)(smem + S_PART +
                    (((warp << 3) + (lane >> 2)) << 1)) = pv;
            __syncthreads();

            // stats: 8 threads combine 10 warp-partials each
            if (tid < HTOK) {
                float sum = 0.f, sq = 0.f;
                #pragma unroll
                for (int w2 = 0; w2 < NWARP; ++w2) {
                    float2 pr = ((const float2*)(smem + S_PART))[(w2 << 3) + tid];
                    sum += pr.x; sq += pr.y;
                }
                float mean = sum * (1.f / 300.f);
                float var  = sq * (1.f / 300.f) - mean * mean;
                ((float2*)(smem + S_STAT))[tid] =
                    make_float2(mean, rsqrtf(var + 1e-5f));
            }
            __syncthreads();

            // accumulate softmax-weighted LN output
            {
                const float4* st4 = (const float4*)(smem + S_STAT);
                const float4* wt4 = (const float4*)(smem + S_WT + f * 16 + tbase);
                #pragma unroll
                for (int c = 0; c < 2; ++c) {
                    float4 wt = wt4[c];
                    float4 sa = st4[2 * c], sb = st4[2 * c + 1];
                    acc[4*c+0] = fmaf(y[4*c+0] - sa.x, sa.y * lng * wt.x, fmaf(lnb, wt.x, acc[4*c+0]));
                    acc[4*c+1] = fmaf(y[4*c+1] - sa.z, sa.w * lng * wt.y, fmaf(lnb, wt.y, acc[4*c+1]));
                    acc[4*c+2] = fmaf(y[4*c+2] - sb.x, sb.y * lng * wt.z, fmaf(lnb, wt.z, acc[4*c+2]));
                    acc[4*c+3] = fmaf(y[4*c+3] - sb.z, sb.w * lng * wt.w, fmaf(lnb, wt.w, acc[4*c+3]));
                }
            }
        }

        if (d < ND) {
            #pragma unroll
            for (int t = 0; t < HTOK; ++t)
                out[(token_base + tbase + t) * ND + d] = acc[t];
        }
        __syncthreads();
    }
}

// ---------------------------------------------------------------------------
extern "C" void kernel_launch(void* const* d_in, const int* in_sizes, int n_in,
                              void* d_out, int out_size)
{
    const float* x         = (const float*)d_in[0];
    const float* pre_w     = (const float*)d_in[1];
    const float* pre_b     = (const float*)d_in[2];
    const float* sg_fc1_w  = (const float*)d_in[3];
    const float* sg_fc1_b  = (const float*)d_in[4];
    const float* sg_fc2_w  = (const float*)d_in[5];
    const float* sg_fc2_b  = (const float*)d_in[6];
    const float* sg_gate_w = (const float*)d_in[7];
    const float* sg_gate_b = (const float*)d_in[8];
    const float* sg_ln_g   = (const float*)d_in[9];
    const float* sg_ln_b   = (const float*)d_in[10];
    const float* fl_fc1_w  = (const float*)d_in[11];
    const float* fl_fc1_b  = (const float*)d_in[12];
    const float* fl_fc2_w  = (const float*)d_in[13];
    const float* fl_fc2_b  = (const float*)d_in[14];
    const float* fl_gate_w = (const float*)d_in[15];
    const float* fl_gate_b = (const float*)d_in[16];
    const float* fl_ln_g   = (const float*)d_in[17];
    const float* fl_ln_b   = (const float*)d_in[18];

    float* out   = (float*)d_out;                 // [16384, 300]
    float* out_w = out + (size_t)NTOK * ND;       // [16384, 32]

    fuse_weights_kernel<<<dim3(NF, 9), 256>>>(sg_fc2_w, sg_fc2_b, sg_gate_w,
                                              sg_gate_b, sg_ln_g, sg_ln_b);

    size_t smem_bytes = (size_t)SMEMF * sizeof(float);  // 68288
    cudaFuncSetAttribute(vsn_main_kernel,
                         cudaFuncAttributeMaxDynamicSharedMemorySize,
                         (int)smem_bytes);
    vsn_main_kernel<<<NTOK / TOKS, NTHR, smem_bytes>>>(
        x, pre_w, pre_b, sg_fc1_w, sg_fc1_b,
        fl_fc1_w, fl_fc1_b, fl_fc2_w, fl_fc2_b, fl_gate_w, fl_gate_b,
        fl_ln_g, fl_ln_b, out, out_w);
}

// round 17
// speedup vs baseline: 1.0541x; 1.0541x over previous
#include <cuda_runtime.h>
#include <math.h>

// Problem constants
#define NTOK   16384      // B*S
#define NF     32         // features
#define NH     8          // hidden
#define ND     300        // n_dim_model
#define N2D    600        // 2*D
#define NWARP  10
#define NTHR   320
#define TOKS   16         // tokens per block
#define HTOK   8          // tokens per phase-4 half-pass

// Shared layout (float offsets)
#define S_PRET 0          // [256][16] prescaler transposed             (4096)
#define S_H1   4096       // [32 f][8 j][16 t] h1 (no duplication)      (4096)
#define S_WT   8192       // [32 f][16 t] softmax weights transposed    (512)
#define S_PART 8704       // [10 w][8 t] float2 LN partials             (160)
#define S_STAT 8864       // [8 t] float2 (mean, inv)                   (16)
#define S_FLW  8880       // [256][32] fl_fc1_w staging                 (8192)
#define SMEMF  17072      // total floats (68288 bytes)

// Lane-sliced fused gate weights: [f][warp][chunk(5)][lane(32)][4 floats]
// Per-lane record (d = warp*32+lane), 20 floats:
//   floats 0..15 : (wA_j, wB_j) pairs, j=0..7
//   floats 16,17 : fused gate bias (gA, gB) = b2@Wg + bg
//   floats 18,19 : ln_g, ln_b
// Pad region d in [300,320) never written -> stays zero (zero-init globals).
__device__ float g_W2[NF * NWARP * 5 * 32 * 4];   // 819 KB

// ---------------------------------------------------------------------------
// packed f32x2 helpers (sm_100+)
// ---------------------------------------------------------------------------
__device__ __forceinline__ unsigned long long ffma2(unsigned long long a,
                                                    unsigned long long b,
                                                    unsigned long long c) {
    unsigned long long d;
    asm("fma.rn.f32x2 %0, %1, %2, %3;" : "=l"(d) : "l"(a), "l"(b), "l"(c));
    return d;
}
__device__ __forceinline__ unsigned long long fadd2(unsigned long long a,
                                                    unsigned long long b) {
    unsigned long long d;
    asm("add.rn.f32x2 %0, %1, %2;" : "=l"(d) : "l"(a), "l"(b));
    return d;
}
__device__ __forceinline__ unsigned long long pack2(float lo, float hi) {
    unsigned long long r;
    asm("mov.b64 %0, {%1, %2};" : "=l"(r) : "f"(lo), "f"(hi));
    return r;
}
__device__ __forceinline__ void unpack2(unsigned long long v, float& lo, float& hi) {
    asm("mov.b64 {%0, %1}, %2;" : "=f"(lo), "=f"(hi) : "l"(v));
}

// ---------------------------------------------------------------------------
// Packed folding 8-token warp reduction: sp[t] holds (y, y*y) for token t.
// Returns packed (sum, sq) over all 32 lanes for token (lane>>2).
// ---------------------------------------------------------------------------
__device__ __forceinline__ unsigned long long fold8p(unsigned long long s[HTOK],
                                                     int lane) {
    {   const bool hi = (lane & 16) != 0;
        #pragma unroll
        for (int i = 0; i < 4; ++i) {
            unsigned long long sv = hi ? s[i] : s[i + 4];
            unsigned long long rv = __shfl_xor_sync(0xffffffffu, sv, 16);
            s[i] = fadd2(hi ? s[i + 4] : s[i], rv);
        }
    }
    {   const bool hi = (lane & 8) != 0;
        #pragma unroll
        for (int i = 0; i < 2; ++i) {
            unsigned long long sv = hi ? s[i] : s[i + 2];
            unsigned long long rv = __shfl_xor_sync(0xffffffffu, sv, 8);
            s[i] = fadd2(hi ? s[i + 2] : s[i], rv);
        }
    }
    {   const bool hi = (lane & 4) != 0;
        unsigned long long sv = hi ? s[0] : s[1];
        unsigned long long rv = __shfl_xor_sync(0xffffffffu, sv, 4);
        s[0] = fadd2(hi ? s[1] : s[0], rv);
    }
    s[0] = fadd2(s[0], __shfl_xor_sync(0xffffffffu, s[0], 2));
    return fadd2(s[0], __shfl_xor_sync(0xffffffffu, s[0], 1));
}

// ---------------------------------------------------------------------------
// Kernel A (v2): fuse W2@Wg + bias row, ONE block per feature (grid 32).
// All 9 j-rows accumulated simultaneously -> Wg read exactly once (9x less
// L2 traffic than the (32,9)-grid version). 256 threads; each owns columns
// n, n+256, n+512(<600).
// ---------------------------------------------------------------------------
__global__ void __launch_bounds__(256)
fuse_weights_kernel(const float* __restrict__ W2,   // [F,8,300]
                    const float* __restrict__ b2,   // [F,300]
                    const float* __restrict__ Wg,   // [F,300,600]
                    const float* __restrict__ bg,   // [F,600]
                    const float* __restrict__ lng,  // [F,300]
                    const float* __restrict__ lnb)  // [F,300]
{
    const int f   = blockIdx.x;
    const int tid = threadIdx.x;
    __shared__ float s_a[300 * 12];   // [k][j] padded to 12 floats (16B-aligned)

    for (int i = tid; i < 2700; i += 256) {
        int k = i / 9, j = i % 9;
        s_a[k * 12 + j] = (j < 8) ? W2[f * (NH * ND) + j * ND + k]
                                  : b2[f * ND + k];
    }
    __syncthreads();

    const float* wgf = Wg + (size_t)f * (ND * N2D);
    const int n0 = tid, n1 = tid + 256, n2 = tid + 512;
    const bool v2 = (n2 < N2D);

    float acc0[9], acc1[9], acc2[9];
    #pragma unroll
    for (int j = 0; j < 9; ++j) { acc0[j] = 0.f; acc1[j] = 0.f; acc2[j] = 0.f; }

    #pragma unroll 2
    for (int k = 0; k < ND; ++k) {
        float w0 = wgf[k * N2D + n0];
        float w1 = wgf[k * N2D + n1];
        float w2 = v2 ? wgf[k * N2D + n2] : 0.f;
        const float4* ap = (const float4*)(s_a + k * 12);
        float4 aA = ap[0], aB = ap[1], aC = ap[2];
        float av[9] = {aA.x, aA.y, aA.z, aA.w, aB.x, aB.y, aB.z, aB.w, aC.x};
        #pragma unroll
        for (int j = 0; j < 9; ++j) {
            acc0[j] = fmaf(av[j], w0, acc0[j]);
            acc1[j] = fmaf(av[j], w1, acc1[j]);
            acc2[j] = fmaf(av[j], w2, acc2[j]);
        }
    }

    #pragma unroll
    for (int c = 0; c < 3; ++c) {
        int n = (c == 0) ? n0 : (c == 1) ? n1 : n2;
        if (n >= N2D) continue;
        float* accp = (c == 0) ? acc0 : (c == 1) ? acc1 : acc2;
        int d  = (n < ND) ? n : (n - ND);
        int hb = (n < ND) ? 0 : 1;
        int w  = d >> 5, lane = d & 31;
        int base = (((f * NWARP + w) * 5) << 7) + (lane << 2);
        #pragma unroll
        for (int j = 0; j < 9; ++j) {
            float val = accp[j];
            if (j == 8) val += bg[f * N2D + n];
            int idx = (j < 8) ? (2 * j + hb) : (16 + hb);
            g_W2[base + ((idx >> 2) << 7) + (idx & 3)] = val;
        }
        if (hb == 0) {
            g_W2[base + (4 << 7) + 2] = lng[f * ND + d];
            g_W2[base + (4 << 7) + 3] = lnb[f * ND + d];
        }
    }
}

// ---------------------------------------------------------------------------
// Kernel B: fused VSN forward (proven R14 form). 16 tokens/block, 320 thr.
// ---------------------------------------------------------------------------
__global__ void __launch_bounds__(NTHR, 2)
vsn_main_kernel(const float* __restrict__ x,        // [NTOK, 32]
                const float* __restrict__ pre_w,    // [32,8]
                const float* __restrict__ pre_b,    // [32,8]
                const float* __restrict__ fc1w,     // [32,8,8]
                const float* __restrict__ fc1b,     // [32,8]
                const float* __restrict__ fl_fc1_w, // [256,32]
                const float* __restrict__ fl_fc1_b, // [32]
                const float* __restrict__ fl_fc2_w, // [32,32]
                const float* __restrict__ fl_fc2_b, // [32]
                const float* __restrict__ fl_gate_w,// [32,64]
                const float* __restrict__ fl_gate_b,// [64]
                const float* __restrict__ fl_ln_g,  // [32]
                const float* __restrict__ fl_ln_b,  // [32]
                float* __restrict__ out,            // [NTOK,300]
                float* __restrict__ out_w)          // [NTOK,32]
{
    extern __shared__ float smem[];
    const int tid  = threadIdx.x;
    const int lane = tid & 31;
    const int warp = tid >> 5;
    const int token_base = blockIdx.x * TOKS;

    // ---- Phase 1: prescaler into s_preT (stride 16), stage fl_fc1_w ----
    for (int idx = tid; idx < 4096; idx += NTHR) {
        int t = idx & 15, r = idx >> 4, f = r >> 3;
        smem[S_PRET + r * 16 + t] =
            fmaf(x[(token_base + t) * 32 + f], pre_w[r], pre_b[r]);
    }
    {
        const float4* src = (const float4*)fl_fc1_w;
        float4* dst = (float4*)(smem + S_FLW);
        for (int i = tid; i < 2048; i += NTHR) dst[i] = src[i];
    }
    __syncthreads();

    // ---- Phase 2: h1 = elu(pre @ fc1 + b) into [f][j][16 t] (no dup) ----
    for (int idx = tid; idx < 4096; idx += NTHR) {
        int t = idx & 15, r = idx >> 4, f = r >> 3, k = r & 7;
        float acc = fc1b[r];
        #pragma unroll
        for (int h = 0; h < 8; ++h)
            acc = fmaf(smem[S_PRET + ((f << 3) + h) * 16 + t],
                       fc1w[(f << 6) + (h << 3) + k], acc);
        float e = acc > 0.f ? acc : expm1f(acc);
        smem[S_H1 + ((f << 3) + k) * 16 + t] = e;
    }

    // ---- Phase 3: flattened GRN + softmax (warps 0..7, 2 tokens each) ----
    if (warp < 8) {
        const int t0 = warp * 2, t1 = t0 + 1;
        float b1 = fl_fc1_b[lane];
        float a0 = b1, a1 = b1;
        #pragma unroll 4
        for (int i = 0; i < 256; ++i) {
            float w = smem[S_FLW + i * 32 + lane];
            float2 p = *(const float2*)(smem + S_PRET + i * 16 + t0);
            a0 = fmaf(p.x, w, a0);
            a1 = fmaf(p.y, w, a1);
        }
        a0 = a0 > 0.f ? a0 : expm1f(a0);
        a1 = a1 > 0.f ? a1 : expm1f(a1);

        float c0 = fl_fc2_b[lane], c1 = c0;
        #pragma unroll
        for (int j = 0; j < 32; ++j) {
            float w = fl_fc2_w[j * 32 + lane];
            c0 = fmaf(__shfl_sync(0xffffffffu, a0, j), w, c0);
            c1 = fmaf(__shfl_sync(0xffffffffu, a1, j), w, c1);
        }

        float ga0 = fl_gate_b[lane], gb0 = fl_gate_b[lane + 32];
        float ga1 = ga0, gb1 = gb0;
        #pragma unroll
        for (int k = 0; k < 32; ++k) {
            float wa = fl_gate_w[k * 64 + lane];
            float wb = fl_gate_w[k * 64 + lane + 32];
            float v0 = __shfl_sync(0xffffffffu, c0, k);
            float v1 = __shfl_sync(0xffffffffu, c1, k);
            ga0 = fmaf(v0, wa, ga0); gb0 = fmaf(v0, wb, gb0);
            ga1 = fmaf(v1, wa, ga1); gb1 = fmaf(v1, wb, gb1);
        }
        float glu0 = __fdividef(ga0, 1.f + __expf(-gb0));
        float glu1 = __fdividef(ga1, 1.f + __expf(-gb1));

        // interp(flat, 256 -> 32)
        float pos = (float)lane * (255.0f / 31.0f);
        int lo = (int)floorf(pos); if (lo > 255) lo = 255;
        int hi = min(lo + 1, 255);
        float wd = pos - (float)lo;
        float2 plo = *(const float2*)(smem + S_PRET + lo * 16 + t0);
        float2 phi = *(const float2*)(smem + S_PRET + hi * 16 + t0);
        float r0 = plo.x * (1.f - wd) + phi.x * wd;
        float r1 = plo.y * (1.f - wd) + phi.y * wd;

        float y0 = glu0 + r0, y1 = glu1 + r1;
        float s0 = y0, q0 = y0 * y0, s1 = y1, q1 = y1 * y1;
        #pragma unroll
        for (int o = 16; o > 0; o >>= 1) {
            s0 += __shfl_xor_sync(0xffffffffu, s0, o);
            q0 += __shfl_xor_sync(0xffffffffu, q0, o);
            s1 += __shfl_xor_sync(0xffffffffu, s1, o);
            q1 += __shfl_xor_sync(0xffffffffu, q1, o);
        }
        float m0 = s0 * (1.f / 32.f), v0 = q0 * (1.f / 32.f) - m0 * m0;
        float m1 = s1 * (1.f / 32.f), v1 = q1 * (1.f / 32.f) - m1 * m1;
        float wl0 = (y0 - m0) * rsqrtf(v0 + 1e-5f) * fl_ln_g[lane] + fl_ln_b[lane];
        float wl1 = (y1 - m1) * rsqrtf(v1 + 1e-5f) * fl_ln_g[lane] + fl_ln_b[lane];

        float mx0 = wl0, mx1 = wl1;
        #pragma unroll
        for (int o = 16; o > 0; o >>= 1) {
            mx0 = fmaxf(mx0, __shfl_xor_sync(0xffffffffu, mx0, o));
            mx1 = fmaxf(mx1, __shfl_xor_sync(0xffffffffu, mx1, o));
        }
        float e0 = __expf(wl0 - mx0), e1 = __expf(wl1 - mx1);
        float se0 = e0, se1 = e1;
        #pragma unroll
        for (int o = 16; o > 0; o >>= 1) {
            se0 += __shfl_xor_sync(0xffffffffu, se0, o);
            se1 += __shfl_xor_sync(0xffffffffu, se1, o);
        }
        float w0 = __fdividef(e0, se0), w1 = __fdividef(e1, se1);
        smem[S_WT + lane * 16 + t0] = w0;
        smem[S_WT + lane * 16 + t1] = w1;
        out_w[(token_base + t0) * 32 + lane] = w0;
        out_w[(token_base + t1) * 32 + lane] = w1;
    }
    __syncthreads();

    // ---- Phase 4: two passes of 8 tokens; lane owns d = warp*32+lane ----
    const int d = (warp << 5) + lane;
    const float actmask = (d < ND) ? 1.0f : 0.0f;
    float posd = (float)d * (7.0f / 299.0f);
    int lod = (int)floorf(posd); if (lod > 7) lod = 7;
    int hid = min(lod + 1, 7);
    float wdd = posd - (float)lod;

    const float* wlane = g_W2 + ((warp * 5) << 7) + (lane << 2);  // f=0 base
    const int    fstep = NWARP * 5 * 128;                          // floats per f

    #pragma unroll 1
    for (int half = 0; half < 2; ++half) {
        const int tbase = half * HTOK;

        float acc[HTOK];
        #pragma unroll
        for (int t = 0; t < HTOK; ++t) acc[t] = 0.f;

        // preload f=0 weight record
        ulonglong2 q0 = *(const ulonglong2*)(wlane);
        ulonglong2 q1 = *(const ulonglong2*)(wlane + 128);
        ulonglong2 q2 = *(const ulonglong2*)(wlane + 256);
        ulonglong2 q3 = *(const ulonglong2*)(wlane + 384);
        ulonglong2 q4 = *(const ulonglong2*)(wlane + 512);

        #pragma unroll 1
        for (int f = 0; f < NF; ++f) {
            // extract all scalars needed after the q overwrite
            float gab, gbb, lng, lnb;
            unpack2(q4.x, gab, gbb);
            unpack2(q4.y, lng, lnb);

            // interp residuals for this half's 8 tokens (float4 rows)
            float s[HTOK];
            {
                const float4* pl4 =
                    (const float4*)(smem + S_PRET + ((f << 3) + lod) * 16 + tbase);
                const float4* ph4 =
                    (const float4*)(smem + S_PRET + ((f << 3) + hid) * 16 + tbase);
                #pragma unroll
                for (int c = 0; c < 2; ++c) {
                    float4 a = pl4[c], b = ph4[c];
                    s[4 * c + 0] = fmaf(wdd, b.x - a.x, a.x);
                    s[4 * c + 1] = fmaf(wdd, b.y - a.y, a.y);
                    s[4 * c + 2] = fmaf(wdd, b.z - a.z, a.z);
                    s[4 * c + 3] = fmaf(wdd, b.w - a.w, a.w);
                }
            }

            // gate: token-pair packed accumulators; h1 pairs loaded directly
            unsigned long long Ab = pack2(gab, gab), Bb = pack2(gbb, gbb);
            unsigned long long A0 = Ab, A1 = Ab, A2 = Ab, A3 = Ab;
            unsigned long long B0 = Bb, B1 = Bb, B2 = Bb, B3 = Bb;

            const float* h1r = smem + S_H1 + (f << 7) + tbase;  // row stride 16

            #define GATE_J(QJ, ROW) do {                                        \
                float wa_, wb_; unpack2((QJ), wa_, wb_);                        \
                unsigned long long wad_ = pack2(wa_, wa_);                      \
                unsigned long long wbd_ = pack2(wb_, wb_);                      \
                ulonglong2 hA_ = *(const ulonglong2*)(ROW);                     \
                ulonglong2 hB_ = *(const ulonglong2*)((ROW) + 4);               \
                A0 = ffma2(hA_.x, wad_, A0);  B0 = ffma2(hA_.x, wbd_, B0);      \
                A1 = ffma2(hA_.y, wad_, A1);  B1 = ffma2(hA_.y, wbd_, B1);      \
                A2 = ffma2(hB_.x, wad_, A2);  B2 = ffma2(hB_.x, wbd_, B2);      \
                A3 = ffma2(hB_.y, wad_, A3);  B3 = ffma2(hB_.y, wbd_, B3);      \
            } while (0)

            GATE_J(q0.x, h1r + 0 * 16);
            GATE_J(q0.y, h1r + 1 * 16);
            GATE_J(q1.x, h1r + 2 * 16);
            GATE_J(q1.y, h1r + 3 * 16);
            GATE_J(q2.x, h1r + 4 * 16);
            GATE_J(q2.y, h1r + 5 * 16);
            GATE_J(q3.x, h1r + 6 * 16);
            GATE_J(q3.y, h1r + 7 * 16);
            #undef GATE_J

            // software pipeline: issue next feature's weight loads NOW
            {
                int fn = (f + 1 < NF) ? (f + 1) : f;
                const float* wn = wlane + fn * fstep;
                q0 = *(const ulonglong2*)(wn);
                q1 = *(const ulonglong2*)(wn + 128);
                q2 = *(const ulonglong2*)(wn + 256);
                q3 = *(const ulonglong2*)(wn + 384);
                q4 = *(const ulonglong2*)(wn + 512);
            }

            float y[HTOK];
            {
                float a0, a1, b0, b1;
                unpack2(A0, a0, a1); unpack2(B0, b0, b1);
                y[0] = (__fdividef(a0, 1.f + __expf(-b0)) + s[0]) * actmask;
                y[1] = (__fdividef(a1, 1.f + __expf(-b1)) + s[1]) * actmask;
                unpack2(A1, a0, a1); unpack2(B1, b0, b1);
                y[2] = (__fdividef(a0, 1.f + __expf(-b0)) + s[2]) * actmask;
                y[3] = (__fdividef(a1, 1.f + __expf(-b1)) + s[3]) * actmask;
                unpack2(A2, a0, a1); unpack2(B2, b0, b1);
                y[4] = (__fdividef(a0, 1.f + __expf(-b0)) + s[4]) * actmask;
                y[5] = (__fdividef(a1, 1.f + __expf(-b1)) + s[5]) * actmask;
                unpack2(A3, a0, a1); unpack2(B3, b0, b1);
                y[6] = (__fdividef(a0, 1.f + __expf(-b0)) + s[6]) * actmask;
                y[7] = (__fdividef(a1, 1.f + __expf(-b1)) + s[7]) * actmask;
            }

            // packed fold: (sum, sq) for all 8 tokens in one reduction
            unsigned long long sp[HTOK];
            #pragma unroll
            for (int t = 0; t < HTOK; ++t) sp[t] = pack2(y[t], y[t] * y[t]);
            unsigned long long pv = fold8p(sp, lane);
            if ((lane & 3) == 0)
                *(unsigned long long*)(smem + S_PART +
                    (((warp << 3) + (lane >> 2)) << 1)) = pv;
            __syncthreads();

            // stats: 8 threads combine 10 warp-partials each
            if (tid < HTOK) {
                float sum = 0.f, sq = 0.f;
                #pragma unroll
                for (int w2 = 0; w2 < NWARP; ++w2) {
                    float2 pr = ((const float2*)(smem + S_PART))[(w2 << 3) + tid];
                    sum += pr.x; sq += pr.y;
                }
                float mean = sum * (1.f / 300.f);
                float var  = sq * (1.f / 300.f) - mean * mean;
                ((float2*)(smem + S_STAT))[tid] =
                    make_float2(mean, rsqrtf(var + 1e-5f));
            }
            __syncthreads();

            // accumulate softmax-weighted LN output
            {
                const float4* st4 = (const float4*)(smem + S_STAT);
                const float4* wt4 = (const float4*)(smem + S_WT + f * 16 + tbase);
                #pragma unroll
                for (int c = 0; c < 2; ++c) {
                    float4 wt = wt4[c];
                    float4 sa = st4[2 * c], sb = st4[2 * c + 1];
                    acc[4*c+0] = fmaf(y[4*c+0] - sa.x, sa.y * lng * wt.x, fmaf(lnb, wt.x, acc[4*c+0]));
                    acc[4*c+1] = fmaf(y[4*c+1] - sa.z, sa.w * lng * wt.y, fmaf(lnb, wt.y, acc[4*c+1]));
                    acc[4*c+2] = fmaf(y[4*c+2] - sb.x, sb.y * lng * wt.z, fmaf(lnb, wt.z, acc[4*c+2]));
                    acc[4*c+3] = fmaf(y[4*c+3] - sb.z, sb.w * lng * wt.w, fmaf(lnb, wt.w, acc[4*c+3]));
                }
            }
        }

        if (d < ND) {
            #pragma unroll
            for (int t = 0; t < HTOK; ++t)
                out[(token_base + tbase + t) * ND + d] = acc[t];
        }
        __syncthreads();
    }
}

// ---------------------------------------------------------------------------
extern "C" void kernel_launch(void* const* d_in, const int* in_sizes, int n_in,
                              void* d_out, int out_size)
{
    const float* x         = (const float*)d_in[0];
    const float* pre_w     = (const float*)d_in[1];
    const float* pre_b     = (const float*)d_in[2];
    const float* sg_fc1_w  = (const float*)d_in[3];
    const float* sg_fc1_b  = (const float*)d_in[4];
    const float* sg_fc2_w  = (const float*)d_in[5];
    const float* sg_fc2_b  = (const float*)d_in[6];
    const float* sg_gate_w = (const float*)d_in[7];
    const float* sg_gate_b = (const float*)d_in[8];
    const float* sg_ln_g   = (const float*)d_in[9];
    const float* sg_ln_b   = (const float*)d_in[10];
    const float* fl_fc1_w  = (const float*)d_in[11];
    const float* fl_fc1_b  = (const float*)d_in[12];
    const float* fl_fc2_w  = (const float*)d_in[13];
    const float* fl_fc2_b  = (const float*)d_in[14];
    const float* fl_gate_w = (const float*)d_in[15];
    const float* fl_gate_b = (const float*)d_in[16];
    const float* fl_ln_g   = (const float*)d_in[17];
    const float* fl_ln_b   = (const float*)d_in[18];

    float* out   = (float*)d_out;                 // [16384, 300]
    float* out_w = out + (size_t)NTOK * ND;       // [16384, 32]

    fuse_weights_kernel<<<NF, 256>>>(sg_fc2_w, sg_fc2_b, sg_gate_w,
                                     sg_gate_b, sg_ln_g, sg_ln_b);

    size_t smem_bytes = (size_t)SMEMF * sizeof(float);  // 68288
    cudaFuncSetAttribute(vsn_main_kernel,
                         cudaFuncAttributeMaxDynamicSharedMemorySize,
                         (int)smem_bytes);
    vsn_main_kernel<<<NTOK / TOKS, NTHR, smem_bytes>>>(
        x, pre_w, pre_b, sg_fc1_w, sg_fc1_b,
        fl_fc1_w, fl_fc1_b, fl_fc2_w, fl_fc2_b, fl_gate_w, fl_gate_b,
        fl_ln_g, fl_ln_b, out, out_w);
}